// round 16
// baseline (speedup 1.0000x reference)
#include <cuda_runtime.h>
#include <cuda_fp16.h>
#include <math.h>
#include <stdint.h>

// ---------------------------------------------------------------------------
#define NROWS 8192
#define DDIM  4096
#define ALPHA 0.2f

#define BM 128
#define BN 256
#define BK 128
#define NST 2

#define A_ST 32768                         // 128 rows * 128 k * 2B
#define B_ST 65536                         // 256 rows * 128 k * 2B
#define A_OFF(s) ((s) * A_ST)
#define B_OFF(s) (NST * A_ST + (s) * B_ST)
#define SMEM_MAIN 196608                   // 2 * 96KB (>= 135KB epilogue restage)

#define KB 256       // DDIM / 16  (fp16 k-blocks of 16)
#define NCHUNK 64
#define CHROWS 128   // NROWS / NCHUNK

// ---------------------------------------------------------------------------
// Scratch globals
// ---------------------------------------------------------------------------
__device__ __half g_Xh[(size_t)NROWS * DDIM];   // fragment-packed fp16 X
__device__ __half g_Wh[(size_t)DDIM * DDIM];    // fragment-packed fp16 W
__device__ __half g_hh[(size_t)NROWS * DDIM];   // h row-major fp16
__device__ float g_s1[NROWS];
__device__ float g_s2[NROWS];
__device__ float g_F1p[NROWS];
__device__ float g_F1n[NROWS];
__device__ float g_E2p[NROWS];
__device__ float g_E2n[NROWS];

// sorted-by-s2-desc structures
__device__ int   g_sIdx[NROWS];
__device__ float g_sS2[NROWS];
__device__ float g_sWp[NROWS];
__device__ float g_sWn[NROWS];
__device__ float g_psP[NROWS + 1];
__device__ float g_psN[NROWS + 1];
__device__ float g_zinv[NROWS];

// emit order (sorted by s1 ascending == cut ascending)
__device__ int   g_r1[NROWS];
__device__ int   g_emit[NROWS];
__device__ int   g_cutS[NROWS];

// chunk sums / prefixes
__device__ float g_CSp[NCHUNK * DDIM];
__device__ float g_CSn[NCHUNK * DDIM];
__device__ float g_CPp[NCHUNK * DDIM];
__device__ float g_CPn[NCHUNK * DDIM];
__device__ float g_TOTn[DDIM];

// ---------------------------------------------------------------------------
__device__ __forceinline__ uint32_t h2u(float a, float b) {
    __half2 h = __floats2half2_rn(a, b);
    return *(uint32_t*)&h;
}

#define CP16(smem_addr, gptr) \
    asm volatile("cp.async.cg.shared.global [%0], [%1], 16;" \
                 :: "r"(smem_addr), "l"(gptr) : "memory")
#define CP_COMMIT() asm volatile("cp.async.commit_group;" ::: "memory")
#define CP_WAITG1() asm volatile("cp.async.wait_group 1;" ::: "memory")

#define MMA_F16(d, av, b0, b1) \
    asm volatile("mma.sync.aligned.m16n8k16.row.col.f32.f16.f16.f32 " \
        "{%0,%1,%2,%3}, {%4,%5,%6,%7}, {%8,%9}, {%0,%1,%2,%3};" \
        : "+f"((d)[0]), "+f"((d)[1]), "+f"((d)[2]), "+f"((d)[3]) \
        : "r"((av).x), "r"((av).y), "r"((av).z), "r"((av).w), \
          "r"(b0), "r"(b1))

// ---------------------------------------------------------------------------
// Merged permute: X -> A-fragment layout, W -> B-fragment layout (one launch)
// ---------------------------------------------------------------------------
__global__ __launch_bounds__(256) void perm_kernel(const float* __restrict__ X,
                                                   const float* __restrict__ W,
                                                   uint4* __restrict__ dA,
                                                   uint4* __restrict__ dB) {
    __shared__ float Ts[16 * 520];
    const int tid = threadIdx.x;
    const int bx = blockIdx.x;
    const int by = blockIdx.y;
    const bool isA = by < (NROWS / 16);
    const int R = isA ? by : by - (NROWS / 16);
    const float* src = isA ? X : W;
    #pragma unroll
    for (int c = 0; c < 8; c++) {
        int id = tid + 256 * c;
        int row = id >> 7, c4 = id & 127;
        float4 v = *(const float4*)&src[((size_t)(R * 16 + row)) * DDIM + bx * 512 + c4 * 4];
        *(float4*)&Ts[row * 520 + c4 * 4] = v;
    }
    __syncthreads();
    #pragma unroll
    for (int c = 0; c < 4; c++) {
        int id = tid + 256 * c;
        int l = id & 31, kb = id >> 5;
        int g = l >> 2, q = l & 3;
        int k0 = kb * 16;
        uint32_t e00 = h2u(Ts[g * 520 + k0 + 2 * q],           Ts[g * 520 + k0 + 2 * q + 1]);
        uint32_t e01 = h2u(Ts[g * 520 + k0 + 8 + 2 * q],       Ts[g * 520 + k0 + 9 + 2 * q]);
        uint32_t e10 = h2u(Ts[(g + 8) * 520 + k0 + 2 * q],     Ts[(g + 8) * 520 + k0 + 2 * q + 1]);
        uint32_t e11 = h2u(Ts[(g + 8) * 520 + k0 + 8 + 2 * q], Ts[(g + 8) * 520 + k0 + 9 + 2 * q]);
        uint4 v;
        if (isA) { v.x = e00; v.y = e10; v.z = e01; v.w = e11; }
        else     { v.x = e00; v.y = e01; v.z = e10; v.w = e11; }
        uint4* dst = isA ? dA : dB;
        dst[((size_t)R * KB + bx * 32 + kb) * 32 + l] = v;
    }
}

// ---------------------------------------------------------------------------
// GEMM1: h = X @ W^T  (fp16 mma.m16n8k16, 128x256 tiles, BK=128, 2-stage)
// Epilogue writes h as fp16 row-major (g_hh).  [measured-best config]
// ---------------------------------------------------------------------------
__global__ __launch_bounds__(256, 1) void gemm1_kernel() {
    extern __shared__ char smem[];
    const uint32_t sb = (uint32_t)__cvta_generic_to_shared(smem);
    const int tid = threadIdx.x, lane = tid & 31, wid = tid >> 5;
    const int warpM = wid & 1, warpN = wid >> 1;
    const int g = lane >> 2, q = lane & 3;
    const int rowBase = blockIdx.y * BM;
    const int colBase = blockIdx.x * BN;
    const int Rbase = rowBase >> 4, NbBase = colBase >> 4;
    const uint4* Xp4 = (const uint4*)g_Xh;
    const uint4* Wp4 = (const uint4*)g_Wh;
    const int T = DDIM / BK;   // 32

    float acc[4][8][4];
    #pragma unroll
    for (int i = 0; i < 4; i++)
        #pragma unroll
        for (int j = 0; j < 8; j++)
            #pragma unroll
            for (int e = 0; e < 4; e++) acc[i][j][e] = 0.f;

    #define G1_ISSUE(t) do { \
        int st_ = (t) & 1; \
        _Pragma("unroll") \
        for (int c_ = 0; c_ < 8; c_++) { \
            int id_ = tid + 256 * c_; \
            int l_ = id_ & 31, kb_ = (id_ >> 5) & 7, R_ = id_ >> 8; \
            CP16(sb + A_OFF(st_) + id_ * 16, \
                 Xp4 + ((size_t)(Rbase + R_) * KB + (t) * 8 + kb_) * 32 + l_); \
        } \
        _Pragma("unroll") \
        for (int c_ = 0; c_ < 16; c_++) { \
            int id_ = tid + 256 * c_; \
            int l_ = id_ & 31, kb_ = (id_ >> 5) & 7, Nb_ = id_ >> 8; \
            CP16(sb + B_OFF(st_) + id_ * 16, \
                 Wp4 + ((size_t)(NbBase + Nb_) * KB + (t) * 8 + kb_) * 32 + l_); \
        } \
    } while (0)

    G1_ISSUE(0); CP_COMMIT();
    G1_ISSUE(1); CP_COMMIT();

    for (int t = 0; t < T; t++) {
        CP_WAITG1();
        __syncthreads();

        const int st = t & 1;
        const uint4* As = (const uint4*)(smem + A_OFF(st));
        const uint4* Bs = (const uint4*)(smem + B_OFF(st));
        #pragma unroll
        for (int kk = 0; kk < 8; kk++) {
            uint4 av[4], bv[4];
            #pragma unroll
            for (int fm = 0; fm < 4; fm++)
                av[fm] = As[((warpM * 4 + fm) * 8 + kk) * 32 + lane];
            #pragma unroll
            for (int p = 0; p < 4; p++)
                bv[p] = Bs[((warpN * 4 + p) * 8 + kk) * 32 + lane];
            #pragma unroll
            for (int fm = 0; fm < 4; fm++)
                #pragma unroll
                for (int p = 0; p < 4; p++) {
                    MMA_F16(acc[fm][2 * p],     av[fm], bv[p].x, bv[p].y);
                    MMA_F16(acc[fm][2 * p + 1], av[fm], bv[p].z, bv[p].w);
                }
        }

        __syncthreads();
        int tn = t + 2;
        if (tn < T) { G1_ISSUE(tn); }
        CP_COMMIT();
    }
    #undef G1_ISSUE

    // Epilogue: restage in smem (fp32), convert + write fp16 h (coalesced uint4)
    __syncthreads();
    float* Hs = (float*)smem;          // stride 264 floats (135KB < 192KB)
    #pragma unroll
    for (int fm = 0; fm < 4; fm++) {
        int r = warpM * 64 + fm * 16 + g;
        #pragma unroll
        for (int fn = 0; fn < 8; fn++) {
            int c = warpN * 64 + fn * 8 + 2 * q;
            *(float2*)&Hs[r * 264 + c]       = *(float2*)&acc[fm][fn][0];
            *(float2*)&Hs[(r + 8) * 264 + c] = *(float2*)&acc[fm][fn][2];
        }
    }
    __syncthreads();
    #pragma unroll
    for (int p = 0; p < 16; p++) {
        int idx = tid + p * 256;
        int row = idx >> 5, ch = idx & 31;
        const float* src = &Hs[row * 264 + ch * 8];
        float4 v0 = *(const float4*)src;
        float4 v1 = *(const float4*)(src + 4);
        uint4 o;
        o.x = h2u(v0.x, v0.y);
        o.y = h2u(v0.z, v0.w);
        o.z = h2u(v1.x, v1.y);
        o.w = h2u(v1.z, v1.w);
        *(uint4*)&g_hh[(size_t)(rowBase + row) * DDIM + colBase + ch * 8] = o;
    }
}

// ---------------------------------------------------------------------------
// s1/s2: one warp per row of hh (fp16)
// ---------------------------------------------------------------------------
__global__ __launch_bounds__(256) void s12_kernel(const float* __restrict__ a) {
    const int wid = threadIdx.x >> 5, lane = threadIdx.x & 31;
    const int i = blockIdx.x * 8 + wid;
    const __half* hr = g_hh + (size_t)i * DDIM;
    float s1 = 0.f, s2 = 0.f;
    #pragma unroll 4
    for (int kb = 0; kb < 16; kb++) {
        int idx = kb * 256 + lane * 8;
        uint4 hv = *(const uint4*)&hr[idx];
        const __half2* h2 = (const __half2*)&hv;
        float2 f0 = __half22float2(h2[0]);
        float2 f1 = __half22float2(h2[1]);
        float2 f2 = __half22float2(h2[2]);
        float2 f3 = __half22float2(h2[3]);
        float4 a1a = *(const float4*)&a[idx];
        float4 a1b = *(const float4*)&a[idx + 4];
        float4 a2a = *(const float4*)&a[DDIM + idx];
        float4 a2b = *(const float4*)&a[DDIM + idx + 4];
        s1 += f0.x * a1a.x + f0.y * a1a.y + f1.x * a1a.z + f1.y * a1a.w
            + f2.x * a1b.x + f2.y * a1b.y + f3.x * a1b.z + f3.y * a1b.w;
        s2 += f0.x * a2a.x + f0.y * a2a.y + f1.x * a2a.z + f1.y * a2a.w
            + f2.x * a2b.x + f2.y * a2b.y + f3.x * a2b.z + f3.y * a2b.w;
    }
    #pragma unroll
    for (int s = 16; s > 0; s >>= 1) {
        s1 += __shfl_xor_sync(0xffffffffu, s1, s);
        s2 += __shfl_xor_sync(0xffffffffu, s2, s);
    }
    if (lane == 0) { g_s1[i] = s1; g_s2[i] = s2; }
}

// ---------------------------------------------------------------------------
// Fused max(s2) + per-row softmax factor precompute (single block)
// ---------------------------------------------------------------------------
__global__ __launch_bounds__(1024) void prep_kernel() {
    __shared__ float sm[1024];
    const int tid = threadIdx.x;
    float m = -1e30f;
    #pragma unroll
    for (int c = 0; c < 8; c++) m = fmaxf(m, g_s2[tid + c * 1024]);
    sm[tid] = m;
    __syncthreads();
    for (int s = 512; s > 0; s >>= 1) {
        if (tid < s) sm[tid] = fmaxf(sm[tid], sm[tid + s]);
        __syncthreads();
    }
    const float m2 = sm[0];
    #pragma unroll
    for (int c = 0; c < 8; c++) {
        int i = tid + c * 1024;
        const float s1v = g_s1[i], s2v = g_s2[i];
        const float t = s1v + m2;
        const float M = (t > 0.f) ? t : ALPHA * t;
        g_F1p[i] = expf(s1v - M);
        g_F1n[i] = expf(ALPHA * s1v - M);
        g_E2p[i] = expf(s2v);
        g_E2n[i] = expf(ALPHA * s2v);
    }
}

// ---------------------------------------------------------------------------
// Dual rank: by s2 desc and by s1 asc
// ---------------------------------------------------------------------------
__global__ __launch_bounds__(256) void rank2_kernel() {
    __shared__ float t2[1024], t1[1024];
    const int j = blockIdx.x * 256 + threadIdx.x;
    const float v2 = g_s2[j];
    const float v1 = g_s1[j];
    int c2 = 0, c1 = 0;
    for (int c0 = 0; c0 < NROWS; c0 += 1024) {
        for (int k = threadIdx.x; k < 1024; k += 256) {
            t2[k] = g_s2[c0 + k];
            t1[k] = g_s1[c0 + k];
        }
        __syncthreads();
        #pragma unroll 4
        for (int k = 0; k < 1024; k++) {
            float u2 = t2[k], u1 = t1[k];
            c2 += (u2 > v2) || (u2 == v2 && (c0 + k) < j);
            c1 += (u1 < v1) || (u1 == v1 && (c0 + k) < j);
        }
        __syncthreads();
    }
    g_sIdx[c2] = j;
    g_sS2[c2] = v2;
    g_sWp[c2] = g_E2p[j];
    g_sWn[c2] = g_E2n[j];
    g_r1[j] = c1;
}

// ---------------------------------------------------------------------------
__global__ __launch_bounds__(256) void sscan_kernel() {
    __shared__ float pp[256], pn[256];
    const int t = threadIdx.x;
    const int base = t * 32;
    float lp = 0.f, ln = 0.f;
    for (int k = 0; k < 32; k++) { lp += g_sWp[base + k]; ln += g_sWn[base + k]; }
    pp[t] = lp; pn[t] = ln;
    __syncthreads();
    for (int off = 1; off < 256; off <<= 1) {
        float vp = (t >= off) ? pp[t - off] : 0.f;
        float vn = (t >= off) ? pn[t - off] : 0.f;
        __syncthreads();
        pp[t] += vp; pn[t] += vn;
        __syncthreads();
    }
    float rp = (t > 0) ? pp[t - 1] : 0.f;
    float rn = (t > 0) ? pn[t - 1] : 0.f;
    for (int k = 0; k < 32; k++) {
        g_psP[base + k] = rp;
        g_psN[base + k] = rn;
        rp += g_sWp[base + k];
        rn += g_sWn[base + k];
    }
    if (t == 255) { g_psP[NROWS] = rp; g_psN[NROWS] = rn; }
}

// ---------------------------------------------------------------------------
__global__ __launch_bounds__(256) void cut_kernel() {
    const int i = blockIdx.x * 256 + threadIdx.x;
    const float thr = -g_s1[i];
    int lo = 0, hi = NROWS;
    while (lo < hi) {
        int mid = (lo + hi) >> 1;
        if (g_sS2[mid] > thr) lo = mid + 1; else hi = mid;
    }
    const int c = lo;
    const float zp = g_psP[c];
    const float zn = g_psN[NROWS] - g_psN[c];
    const float z = g_F1p[i] * zp + g_F1n[i] * zn;
    g_zinv[i] = 1.0f / z;
    const int r1 = g_r1[i];
    g_emit[r1] = i;
    g_cutS[r1] = c;
}

// ---------------------------------------------------------------------------
// Chunk sums: 4 columns per thread (uint2 h loads, float4 stores)
// ---------------------------------------------------------------------------
__global__ __launch_bounds__(256) void chunksum_kernel() {
    __shared__ float wp[CHROWS], wn[CHROWS];
    __shared__ int ridx[CHROWS];
    const int K = blockIdx.y;
    const int cb = blockIdx.x * 1024;
    const int tid = threadIdx.x;
    if (tid < CHROWS) {
        wp[tid] = g_sWp[K * CHROWS + tid];
        wn[tid] = g_sWn[K * CHROWS + tid];
        ridx[tid] = g_sIdx[K * CHROWS + tid];
    }
    __syncthreads();
    const int c0 = cb + 4 * tid;
    float4 ap = make_float4(0.f, 0.f, 0.f, 0.f);
    float4 an = make_float4(0.f, 0.f, 0.f, 0.f);
    #pragma unroll 2
    for (int r = 0; r < CHROWS; r++) {
        const __half* hrow = g_hh + (size_t)ridx[r] * DDIM;
        uint2 hv = *(const uint2*)&hrow[c0];
        float2 h01 = __half22float2(((const __half2*)&hv)[0]);
        float2 h23 = __half22float2(((const __half2*)&hv)[1]);
        const float w_p = wp[r], w_n = wn[r];
        ap.x += w_p * h01.x; an.x += w_n * h01.x;
        ap.y += w_p * h01.y; an.y += w_n * h01.y;
        ap.z += w_p * h23.x; an.z += w_n * h23.x;
        ap.w += w_p * h23.y; an.w += w_n * h23.y;
    }
    *(float4*)&g_CSp[K * DDIM + c0] = ap;
    *(float4*)&g_CSn[K * DDIM + c0] = an;
}

// ---------------------------------------------------------------------------
__global__ __launch_bounds__(256) void chunkscan_kernel() {
    const int col = blockIdx.x * 256 + threadIdx.x;
    float rp = 0.f, rn = 0.f;
    for (int K = 0; K < NCHUNK; K++) {
        g_CPp[K * DDIM + col] = rp;
        g_CPn[K * DDIM + col] = rn;
        rp += g_CSp[K * DDIM + col];
        rn += g_CSn[K * DDIM + col];
    }
    g_TOTn[col] = rn;
}

// ---------------------------------------------------------------------------
// Fused scan + emit: 4 columns per thread (float4 out writes)
// ---------------------------------------------------------------------------
__global__ __launch_bounds__(256) void sweep_kernel(float* __restrict__ out) {
    __shared__ float wp[CHROWS], wn[CHROWS];
    __shared__ int ridx[CHROWS];
    __shared__ int sPlo, sPhi;
    const int K = blockIdx.y;
    const int cb = blockIdx.x * 1024;
    const int tid = threadIdx.x;
    if (tid < CHROWS) {
        wp[tid] = g_sWp[K * CHROWS + tid];
        wn[tid] = g_sWn[K * CHROWS + tid];
        ridx[tid] = g_sIdx[K * CHROWS + tid];
    }
    if (tid == 0) {
        int v = K * CHROWS;
        int lo = 0, hi = NROWS;
        while (lo < hi) { int m = (lo + hi) >> 1; if (g_cutS[m] < v) lo = m + 1; else hi = m; }
        sPlo = lo;
        if (K == NCHUNK - 1) {
            sPhi = NROWS;
        } else {
            v = (K + 1) * CHROWS;
            lo = 0; hi = NROWS;
            while (lo < hi) { int m = (lo + hi) >> 1; if (g_cutS[m] < v) lo = m + 1; else hi = m; }
            sPhi = lo;
        }
    }
    __syncthreads();
    const int c0 = cb + 4 * tid;
    float4 rpv = *(const float4*)&g_CPp[K * DDIM + c0];
    float4 rnv = *(const float4*)&g_CPn[K * DDIM + c0];
    const float4 tot = *(const float4*)&g_TOTn[c0];
    int p = sPlo;
    const int pHi = sPhi;

    for (int r = 0; r < CHROWS; r++) {
        const int rglob = K * CHROWS + r;
        while (p < pHi && g_cutS[p] == rglob) {
            const int i = g_emit[p];
            const float zi = g_zinv[i], f1p = g_F1p[i], f1n = g_F1n[i];
            float4 o;
            o.x = (f1p * rpv.x + f1n * (tot.x - rnv.x)) * zi;
            o.y = (f1p * rpv.y + f1n * (tot.y - rnv.y)) * zi;
            o.z = (f1p * rpv.z + f1n * (tot.z - rnv.z)) * zi;
            o.w = (f1p * rpv.w + f1n * (tot.w - rnv.w)) * zi;
            *(float4*)&out[(size_t)i * DDIM + c0] = o;
            p++;
        }
        const __half* hrow = g_hh + (size_t)ridx[r] * DDIM;
        uint2 hv = *(const uint2*)&hrow[c0];
        float2 h01 = __half22float2(((const __half2*)&hv)[0]);
        float2 h23 = __half22float2(((const __half2*)&hv)[1]);
        const float w_p = wp[r], w_n = wn[r];
        rpv.x += w_p * h01.x; rnv.x += w_n * h01.x;
        rpv.y += w_p * h01.y; rnv.y += w_n * h01.y;
        rpv.z += w_p * h23.x; rnv.z += w_n * h23.x;
        rpv.w += w_p * h23.y; rnv.w += w_n * h23.y;
    }
    while (p < pHi) {
        const int i = g_emit[p];
        const float zi = g_zinv[i], f1p = g_F1p[i], f1n = g_F1n[i];
        float4 o;
        o.x = (f1p * rpv.x + f1n * (tot.x - rnv.x)) * zi;
        o.y = (f1p * rpv.y + f1n * (tot.y - rnv.y)) * zi;
        o.z = (f1p * rpv.z + f1n * (tot.z - rnv.z)) * zi;
        o.w = (f1p * rpv.w + f1n * (tot.w - rnv.w)) * zi;
        *(float4*)&out[(size_t)i * DDIM + c0] = o;
        p++;
    }
}

// ---------------------------------------------------------------------------
extern "C" void kernel_launch(void* const* d_in, const int* in_sizes, int n_in,
                              void* d_out, int out_size) {
    const float* x = nullptr;
    const float* W = nullptr;
    const float* a = nullptr;
    for (int i = 0; i < n_in; i++) {
        if (in_sizes[i] == 33554432)      x = (const float*)d_in[i];
        else if (in_sizes[i] == 16777216) W = (const float*)d_in[i];
        else if (in_sizes[i] == 8192)     a = (const float*)d_in[i];
    }
    float* out = (float*)d_out;

    static bool attr_done = false;
    if (!attr_done) {
        cudaFuncSetAttribute(gemm1_kernel, cudaFuncAttributeMaxDynamicSharedMemorySize, SMEM_MAIN);
        attr_done = true;
    }

    void* xp; cudaGetSymbolAddress(&xp, g_Xh);
    void* wp; cudaGetSymbolAddress(&wp, g_Wh);

    perm_kernel<<<dim3(8, NROWS / 16 + DDIM / 16), 256>>>(x, W, (uint4*)xp, (uint4*)wp);

    dim3 grid(DDIM / BN, NROWS / BM);   // (16, 64)
    gemm1_kernel<<<grid, 256, SMEM_MAIN>>>();

    s12_kernel<<<NROWS / 8, 256>>>(a);
    prep_kernel<<<1, 1024>>>();
    rank2_kernel<<<NROWS / 256, 256>>>();
    sscan_kernel<<<1, 256>>>();
    cut_kernel<<<NROWS / 256, 256>>>();
    chunksum_kernel<<<dim3(DDIM / 1024, NCHUNK), 256>>>();
    chunkscan_kernel<<<DDIM / 256, 256>>>();
    sweep_kernel<<<dim3(DDIM / 1024, NCHUNK), 256>>>(out);
}

// round 17
// speedup vs baseline: 1.0420x; 1.0420x over previous
#include <cuda_runtime.h>
#include <cuda_fp16.h>
#include <math.h>
#include <stdint.h>

// ---------------------------------------------------------------------------
#define NROWS 8192
#define DDIM  4096
#define ALPHA 0.2f

#define BM 128
#define BN 256
#define BK 128
#define NST 2

#define A_ST 32768                         // 128 rows * 128 k * 2B
#define B_ST 65536                         // 256 rows * 128 k * 2B
#define A_OFF(s) ((s) * A_ST)
#define B_OFF(s) (NST * A_ST + (s) * B_ST)
#define SMEM_MAIN 196608                   // 2 * 96KB (>= 135KB epilogue restage)

#define KB 256       // DDIM / 16  (fp16 k-blocks of 16)
#define NCHUNK 64
#define CHROWS 128   // NROWS / NCHUNK

// ---------------------------------------------------------------------------
// Scratch globals
// ---------------------------------------------------------------------------
__device__ __half g_Xh[(size_t)NROWS * DDIM];   // fragment-packed fp16 X
__device__ __half g_Wh[(size_t)DDIM * DDIM];    // fragment-packed fp16 W
__device__ __half g_hh[(size_t)NROWS * DDIM];   // h row-major fp16
__device__ float g_s1[NROWS];
__device__ float g_s2[NROWS];
__device__ float g_F1p[NROWS];
__device__ float g_F1n[NROWS];
__device__ float g_E2p[NROWS];
__device__ float g_E2n[NROWS];

// sorted-by-s2-desc structures
__device__ int   g_sIdx[NROWS];
__device__ float g_sS2[NROWS];
__device__ float g_sWp[NROWS];
__device__ float g_sWn[NROWS];
__device__ float g_psP[NROWS + 1];
__device__ float g_psN[NROWS + 1];
__device__ float g_zinv[NROWS];

// emit order (sorted by s1 ascending == cut ascending)
__device__ int   g_r1[NROWS];
__device__ int   g_emit[NROWS];
__device__ int   g_cutS[NROWS];

// chunk sums / prefixes
__device__ float g_CSp[NCHUNK * DDIM];
__device__ float g_CSn[NCHUNK * DDIM];
__device__ float g_CPp[NCHUNK * DDIM];
__device__ float g_CPn[NCHUNK * DDIM];
__device__ float g_TOTn[DDIM];

// ---------------------------------------------------------------------------
__device__ __forceinline__ uint32_t h2u(float a, float b) {
    __half2 h = __floats2half2_rn(a, b);
    return *(uint32_t*)&h;
}

#define CP16(smem_addr, gptr) \
    asm volatile("cp.async.cg.shared.global [%0], [%1], 16;" \
                 :: "r"(smem_addr), "l"(gptr) : "memory")
#define CP_COMMIT() asm volatile("cp.async.commit_group;" ::: "memory")
#define CP_WAITG1() asm volatile("cp.async.wait_group 1;" ::: "memory")

#define MMA_F16(d, av, b0, b1) \
    asm volatile("mma.sync.aligned.m16n8k16.row.col.f32.f16.f16.f32 " \
        "{%0,%1,%2,%3}, {%4,%5,%6,%7}, {%8,%9}, {%0,%1,%2,%3};" \
        : "+f"((d)[0]), "+f"((d)[1]), "+f"((d)[2]), "+f"((d)[3]) \
        : "r"((av).x), "r"((av).y), "r"((av).z), "r"((av).w), \
          "r"(b0), "r"(b1))

// ---------------------------------------------------------------------------
// Merged permute: X -> A-fragment layout, W -> B-fragment layout (one launch)
// ---------------------------------------------------------------------------
__global__ __launch_bounds__(256) void perm_kernel(const float* __restrict__ X,
                                                   const float* __restrict__ W,
                                                   uint4* __restrict__ dA,
                                                   uint4* __restrict__ dB) {
    __shared__ float Ts[16 * 520];
    const int tid = threadIdx.x;
    const int bx = blockIdx.x;
    const int by = blockIdx.y;
    const bool isA = by < (NROWS / 16);
    const int R = isA ? by : by - (NROWS / 16);
    const float* src = isA ? X : W;
    #pragma unroll
    for (int c = 0; c < 8; c++) {
        int id = tid + 256 * c;
        int row = id >> 7, c4 = id & 127;
        float4 v = *(const float4*)&src[((size_t)(R * 16 + row)) * DDIM + bx * 512 + c4 * 4];
        *(float4*)&Ts[row * 520 + c4 * 4] = v;
    }
    __syncthreads();
    #pragma unroll
    for (int c = 0; c < 4; c++) {
        int id = tid + 256 * c;
        int l = id & 31, kb = id >> 5;
        int g = l >> 2, q = l & 3;
        int k0 = kb * 16;
        uint32_t e00 = h2u(Ts[g * 520 + k0 + 2 * q],           Ts[g * 520 + k0 + 2 * q + 1]);
        uint32_t e01 = h2u(Ts[g * 520 + k0 + 8 + 2 * q],       Ts[g * 520 + k0 + 9 + 2 * q]);
        uint32_t e10 = h2u(Ts[(g + 8) * 520 + k0 + 2 * q],     Ts[(g + 8) * 520 + k0 + 2 * q + 1]);
        uint32_t e11 = h2u(Ts[(g + 8) * 520 + k0 + 8 + 2 * q], Ts[(g + 8) * 520 + k0 + 9 + 2 * q]);
        uint4 v;
        if (isA) { v.x = e00; v.y = e10; v.z = e01; v.w = e11; }
        else     { v.x = e00; v.y = e01; v.z = e10; v.w = e11; }
        uint4* dst = isA ? dA : dB;
        dst[((size_t)R * KB + bx * 32 + kb) * 32 + l] = v;
    }
}

// ---------------------------------------------------------------------------
// GEMM1: h = X @ W^T  (fp16 mma.m16n8k16, 128x256 tiles, BK=128, 2-stage)
// Epilogue writes h as fp16 row-major (g_hh).  [measured-best config]
// ---------------------------------------------------------------------------
__global__ __launch_bounds__(256, 1) void gemm1_kernel() {
    extern __shared__ char smem[];
    const uint32_t sb = (uint32_t)__cvta_generic_to_shared(smem);
    const int tid = threadIdx.x, lane = tid & 31, wid = tid >> 5;
    const int warpM = wid & 1, warpN = wid >> 1;
    const int g = lane >> 2, q = lane & 3;
    const int rowBase = blockIdx.y * BM;
    const int colBase = blockIdx.x * BN;
    const int Rbase = rowBase >> 4, NbBase = colBase >> 4;
    const uint4* Xp4 = (const uint4*)g_Xh;
    const uint4* Wp4 = (const uint4*)g_Wh;
    const int T = DDIM / BK;   // 32

    float acc[4][8][4];
    #pragma unroll
    for (int i = 0; i < 4; i++)
        #pragma unroll
        for (int j = 0; j < 8; j++)
            #pragma unroll
            for (int e = 0; e < 4; e++) acc[i][j][e] = 0.f;

    #define G1_ISSUE(t) do { \
        int st_ = (t) & 1; \
        _Pragma("unroll") \
        for (int c_ = 0; c_ < 8; c_++) { \
            int id_ = tid + 256 * c_; \
            int l_ = id_ & 31, kb_ = (id_ >> 5) & 7, R_ = id_ >> 8; \
            CP16(sb + A_OFF(st_) + id_ * 16, \
                 Xp4 + ((size_t)(Rbase + R_) * KB + (t) * 8 + kb_) * 32 + l_); \
        } \
        _Pragma("unroll") \
        for (int c_ = 0; c_ < 16; c_++) { \
            int id_ = tid + 256 * c_; \
            int l_ = id_ & 31, kb_ = (id_ >> 5) & 7, Nb_ = id_ >> 8; \
            CP16(sb + B_OFF(st_) + id_ * 16, \
                 Wp4 + ((size_t)(NbBase + Nb_) * KB + (t) * 8 + kb_) * 32 + l_); \
        } \
    } while (0)

    G1_ISSUE(0); CP_COMMIT();
    G1_ISSUE(1); CP_COMMIT();

    for (int t = 0; t < T; t++) {
        CP_WAITG1();
        __syncthreads();

        const int st = t & 1;
        const uint4* As = (const uint4*)(smem + A_OFF(st));
        const uint4* Bs = (const uint4*)(smem + B_OFF(st));
        #pragma unroll
        for (int kk = 0; kk < 8; kk++) {
            uint4 av[4], bv[4];
            #pragma unroll
            for (int fm = 0; fm < 4; fm++)
                av[fm] = As[((warpM * 4 + fm) * 8 + kk) * 32 + lane];
            #pragma unroll
            for (int p = 0; p < 4; p++)
                bv[p] = Bs[((warpN * 4 + p) * 8 + kk) * 32 + lane];
            #pragma unroll
            for (int fm = 0; fm < 4; fm++)
                #pragma unroll
                for (int p = 0; p < 4; p++) {
                    MMA_F16(acc[fm][2 * p],     av[fm], bv[p].x, bv[p].y);
                    MMA_F16(acc[fm][2 * p + 1], av[fm], bv[p].z, bv[p].w);
                }
        }

        __syncthreads();
        int tn = t + 2;
        if (tn < T) { G1_ISSUE(tn); }
        CP_COMMIT();
    }
    #undef G1_ISSUE

    // Epilogue: restage in smem (fp32), convert + write fp16 h (coalesced uint4)
    __syncthreads();
    float* Hs = (float*)smem;          // stride 264 floats (135KB < 192KB)
    #pragma unroll
    for (int fm = 0; fm < 4; fm++) {
        int r = warpM * 64 + fm * 16 + g;
        #pragma unroll
        for (int fn = 0; fn < 8; fn++) {
            int c = warpN * 64 + fn * 8 + 2 * q;
            *(float2*)&Hs[r * 264 + c]       = *(float2*)&acc[fm][fn][0];
            *(float2*)&Hs[(r + 8) * 264 + c] = *(float2*)&acc[fm][fn][2];
        }
    }
    __syncthreads();
    #pragma unroll
    for (int p = 0; p < 16; p++) {
        int idx = tid + p * 256;
        int row = idx >> 5, ch = idx & 31;
        const float* src = &Hs[row * 264 + ch * 8];
        float4 v0 = *(const float4*)src;
        float4 v1 = *(const float4*)(src + 4);
        uint4 o;
        o.x = h2u(v0.x, v0.y);
        o.y = h2u(v0.z, v0.w);
        o.z = h2u(v1.x, v1.y);
        o.w = h2u(v1.z, v1.w);
        *(uint4*)&g_hh[(size_t)(rowBase + row) * DDIM + colBase + ch * 8] = o;
    }
}

// ---------------------------------------------------------------------------
// s1/s2: one warp per row of hh (fp16)
// ---------------------------------------------------------------------------
__global__ __launch_bounds__(256) void s12_kernel(const float* __restrict__ a) {
    const int wid = threadIdx.x >> 5, lane = threadIdx.x & 31;
    const int i = blockIdx.x * 8 + wid;
    const __half* hr = g_hh + (size_t)i * DDIM;
    float s1 = 0.f, s2 = 0.f;
    #pragma unroll 4
    for (int kb = 0; kb < 16; kb++) {
        int idx = kb * 256 + lane * 8;
        uint4 hv = *(const uint4*)&hr[idx];
        const __half2* h2 = (const __half2*)&hv;
        float2 f0 = __half22float2(h2[0]);
        float2 f1 = __half22float2(h2[1]);
        float2 f2 = __half22float2(h2[2]);
        float2 f3 = __half22float2(h2[3]);
        float4 a1a = *(const float4*)&a[idx];
        float4 a1b = *(const float4*)&a[idx + 4];
        float4 a2a = *(const float4*)&a[DDIM + idx];
        float4 a2b = *(const float4*)&a[DDIM + idx + 4];
        s1 += f0.x * a1a.x + f0.y * a1a.y + f1.x * a1a.z + f1.y * a1a.w
            + f2.x * a1b.x + f2.y * a1b.y + f3.x * a1b.z + f3.y * a1b.w;
        s2 += f0.x * a2a.x + f0.y * a2a.y + f1.x * a2a.z + f1.y * a2a.w
            + f2.x * a2b.x + f2.y * a2b.y + f3.x * a2b.z + f3.y * a2b.w;
    }
    #pragma unroll
    for (int s = 16; s > 0; s >>= 1) {
        s1 += __shfl_xor_sync(0xffffffffu, s1, s);
        s2 += __shfl_xor_sync(0xffffffffu, s2, s);
    }
    if (lane == 0) { g_s1[i] = s1; g_s2[i] = s2; }
}

// ---------------------------------------------------------------------------
// Fused max(s2) + per-row softmax factor precompute (single block)
// ---------------------------------------------------------------------------
__global__ __launch_bounds__(1024) void prep_kernel() {
    __shared__ float sm[1024];
    const int tid = threadIdx.x;
    float m = -1e30f;
    #pragma unroll
    for (int c = 0; c < 8; c++) m = fmaxf(m, g_s2[tid + c * 1024]);
    sm[tid] = m;
    __syncthreads();
    for (int s = 512; s > 0; s >>= 1) {
        if (tid < s) sm[tid] = fmaxf(sm[tid], sm[tid + s]);
        __syncthreads();
    }
    const float m2 = sm[0];
    #pragma unroll
    for (int c = 0; c < 8; c++) {
        int i = tid + c * 1024;
        const float s1v = g_s1[i], s2v = g_s2[i];
        const float t = s1v + m2;
        const float M = (t > 0.f) ? t : ALPHA * t;
        g_F1p[i] = expf(s1v - M);
        g_F1n[i] = expf(ALPHA * s1v - M);
        g_E2p[i] = expf(s2v);
        g_E2n[i] = expf(ALPHA * s2v);
    }
}

// ---------------------------------------------------------------------------
// Dual rank: by s2 desc and by s1 asc
// ---------------------------------------------------------------------------
__global__ __launch_bounds__(256) void rank2_kernel() {
    __shared__ float t2[1024], t1[1024];
    const int j = blockIdx.x * 256 + threadIdx.x;
    const float v2 = g_s2[j];
    const float v1 = g_s1[j];
    int c2 = 0, c1 = 0;
    for (int c0 = 0; c0 < NROWS; c0 += 1024) {
        for (int k = threadIdx.x; k < 1024; k += 256) {
            t2[k] = g_s2[c0 + k];
            t1[k] = g_s1[c0 + k];
        }
        __syncthreads();
        #pragma unroll 4
        for (int k = 0; k < 1024; k++) {
            float u2 = t2[k], u1 = t1[k];
            c2 += (u2 > v2) || (u2 == v2 && (c0 + k) < j);
            c1 += (u1 < v1) || (u1 == v1 && (c0 + k) < j);
        }
        __syncthreads();
    }
    g_sIdx[c2] = j;
    g_sS2[c2] = v2;
    g_sWp[c2] = g_E2p[j];
    g_sWn[c2] = g_E2n[j];
    g_r1[j] = c1;
}

// ---------------------------------------------------------------------------
__global__ __launch_bounds__(256) void sscan_kernel() {
    __shared__ float pp[256], pn[256];
    const int t = threadIdx.x;
    const int base = t * 32;
    float lp = 0.f, ln = 0.f;
    for (int k = 0; k < 32; k++) { lp += g_sWp[base + k]; ln += g_sWn[base + k]; }
    pp[t] = lp; pn[t] = ln;
    __syncthreads();
    for (int off = 1; off < 256; off <<= 1) {
        float vp = (t >= off) ? pp[t - off] : 0.f;
        float vn = (t >= off) ? pn[t - off] : 0.f;
        __syncthreads();
        pp[t] += vp; pn[t] += vn;
        __syncthreads();
    }
    float rp = (t > 0) ? pp[t - 1] : 0.f;
    float rn = (t > 0) ? pn[t - 1] : 0.f;
    for (int k = 0; k < 32; k++) {
        g_psP[base + k] = rp;
        g_psN[base + k] = rn;
        rp += g_sWp[base + k];
        rn += g_sWn[base + k];
    }
    if (t == 255) { g_psP[NROWS] = rp; g_psN[NROWS] = rn; }
}

// ---------------------------------------------------------------------------
__global__ __launch_bounds__(256) void cut_kernel() {
    const int i = blockIdx.x * 256 + threadIdx.x;
    const float thr = -g_s1[i];
    int lo = 0, hi = NROWS;
    while (lo < hi) {
        int mid = (lo + hi) >> 1;
        if (g_sS2[mid] > thr) lo = mid + 1; else hi = mid;
    }
    const int c = lo;
    const float zp = g_psP[c];
    const float zn = g_psN[NROWS] - g_psN[c];
    const float z = g_F1p[i] * zp + g_F1n[i] * zn;
    g_zinv[i] = 1.0f / z;
    const int r1 = g_r1[i];
    g_emit[r1] = i;
    g_cutS[r1] = c;
}

// ---------------------------------------------------------------------------
// Chunk sums (adjacent-column pairs; row loop software-pipelined x2)
// ---------------------------------------------------------------------------
__global__ __launch_bounds__(256) void chunksum_kernel() {
    __shared__ float wp[CHROWS], wn[CHROWS];
    __shared__ int ridx[CHROWS];
    const int K = blockIdx.y;
    const int cb = blockIdx.x * 512;
    const int tid = threadIdx.x;
    if (tid < CHROWS) {
        wp[tid] = g_sWp[K * CHROWS + tid];
        wn[tid] = g_sWn[K * CHROWS + tid];
        ridx[tid] = g_sIdx[K * CHROWS + tid];
    }
    __syncthreads();
    const int c0 = cb + 2 * tid;
    float ap0 = 0.f, an0 = 0.f, ap1 = 0.f, an1 = 0.f;
    for (int r = 0; r < CHROWS; r += 2) {
        // issue both loads before consuming either (MLP=2)
        uint32_t u0 = *(const uint32_t*)&g_hh[(size_t)ridx[r] * DDIM + c0];
        uint32_t u1 = *(const uint32_t*)&g_hh[(size_t)ridx[r + 1] * DDIM + c0];
        float2 h0 = __half22float2(*(const __half2*)&u0);
        float2 h1 = __half22float2(*(const __half2*)&u1);
        const float wp0 = wp[r], wn0 = wn[r];
        const float wp1 = wp[r + 1], wn1 = wn[r + 1];
        ap0 += wp0 * h0.x; an0 += wn0 * h0.x;
        ap1 += wp0 * h0.y; an1 += wn0 * h0.y;
        ap0 += wp1 * h1.x; an0 += wn1 * h1.x;
        ap1 += wp1 * h1.y; an1 += wn1 * h1.y;
    }
    *(float2*)&g_CSp[K * DDIM + c0] = make_float2(ap0, ap1);
    *(float2*)&g_CSn[K * DDIM + c0] = make_float2(an0, an1);
}

// ---------------------------------------------------------------------------
__global__ __launch_bounds__(256) void chunkscan_kernel() {
    const int col = blockIdx.x * 256 + threadIdx.x;
    float rp = 0.f, rn = 0.f;
    for (int K = 0; K < NCHUNK; K++) {
        g_CPp[K * DDIM + col] = rp;
        g_CPn[K * DDIM + col] = rn;
        rp += g_CSp[K * DDIM + col];
        rn += g_CSn[K * DDIM + col];
    }
    g_TOTn[col] = rn;
}

// ---------------------------------------------------------------------------
// Fused scan + emit (adjacent-column pairs; row loop software-pipelined x2)
// ---------------------------------------------------------------------------
__global__ __launch_bounds__(256) void sweep_kernel(float* __restrict__ out) {
    __shared__ float wp[CHROWS], wn[CHROWS];
    __shared__ int ridx[CHROWS];
    __shared__ int sPlo, sPhi;
    const int K = blockIdx.y;
    const int cb = blockIdx.x * 512;
    const int tid = threadIdx.x;
    if (tid < CHROWS) {
        wp[tid] = g_sWp[K * CHROWS + tid];
        wn[tid] = g_sWn[K * CHROWS + tid];
        ridx[tid] = g_sIdx[K * CHROWS + tid];
    }
    if (tid == 0) {
        int v = K * CHROWS;
        int lo = 0, hi = NROWS;
        while (lo < hi) { int m = (lo + hi) >> 1; if (g_cutS[m] < v) lo = m + 1; else hi = m; }
        sPlo = lo;
        if (K == NCHUNK - 1) {
            sPhi = NROWS;
        } else {
            v = (K + 1) * CHROWS;
            lo = 0; hi = NROWS;
            while (lo < hi) { int m = (lo + hi) >> 1; if (g_cutS[m] < v) lo = m + 1; else hi = m; }
            sPhi = lo;
        }
    }
    __syncthreads();
    const int c0 = cb + 2 * tid;
    float2 rpv = *(const float2*)&g_CPp[K * DDIM + c0];
    float2 rnv = *(const float2*)&g_CPn[K * DDIM + c0];
    const float2 tot = *(const float2*)&g_TOTn[c0];
    int p = sPlo;
    const int pHi = sPhi;

    for (int r = 0; r < CHROWS; r += 2) {
        // issue both rows' loads up front (MLP=2); emits interleave correctly
        uint32_t u0 = *(const uint32_t*)&g_hh[(size_t)ridx[r] * DDIM + c0];
        uint32_t u1 = *(const uint32_t*)&g_hh[(size_t)ridx[r + 1] * DDIM + c0];
        const int rg0 = K * CHROWS + r;
        while (p < pHi && g_cutS[p] == rg0) {
            const int i = g_emit[p];
            const float zi = g_zinv[i], f1p = g_F1p[i], f1n = g_F1n[i];
            float2 o;
            o.x = (f1p * rpv.x + f1n * (tot.x - rnv.x)) * zi;
            o.y = (f1p * rpv.y + f1n * (tot.y - rnv.y)) * zi;
            *(float2*)&out[(size_t)i * DDIM + c0] = o;
            p++;
        }
        {
            float2 h = __half22float2(*(const __half2*)&u0);
            const float w_p = wp[r], w_n = wn[r];
            rpv.x += w_p * h.x; rnv.x += w_n * h.x;
            rpv.y += w_p * h.y; rnv.y += w_n * h.y;
        }
        const int rg1 = rg0 + 1;
        while (p < pHi && g_cutS[p] == rg1) {
            const int i = g_emit[p];
            const float zi = g_zinv[i], f1p = g_F1p[i], f1n = g_F1n[i];
            float2 o;
            o.x = (f1p * rpv.x + f1n * (tot.x - rnv.x)) * zi;
            o.y = (f1p * rpv.y + f1n * (tot.y - rnv.y)) * zi;
            *(float2*)&out[(size_t)i * DDIM + c0] = o;
            p++;
        }
        {
            float2 h = __half22float2(*(const __half2*)&u1);
            const float w_p = wp[r + 1], w_n = wn[r + 1];
            rpv.x += w_p * h.x; rnv.x += w_n * h.x;
            rpv.y += w_p * h.y; rnv.y += w_n * h.y;
        }
    }
    while (p < pHi) {
        const int i = g_emit[p];
        const float zi = g_zinv[i], f1p = g_F1p[i], f1n = g_F1n[i];
        float2 o;
        o.x = (f1p * rpv.x + f1n * (tot.x - rnv.x)) * zi;
        o.y = (f1p * rpv.y + f1n * (tot.y - rnv.y)) * zi;
        *(float2*)&out[(size_t)i * DDIM + c0] = o;
        p++;
    }
}

// ---------------------------------------------------------------------------
extern "C" void kernel_launch(void* const* d_in, const int* in_sizes, int n_in,
                              void* d_out, int out_size) {
    const float* x = nullptr;
    const float* W = nullptr;
    const float* a = nullptr;
    for (int i = 0; i < n_in; i++) {
        if (in_sizes[i] == 33554432)      x = (const float*)d_in[i];
        else if (in_sizes[i] == 16777216) W = (const float*)d_in[i];
        else if (in_sizes[i] == 8192)     a = (const float*)d_in[i];
    }
    float* out = (float*)d_out;

    static bool attr_done = false;
    if (!attr_done) {
        cudaFuncSetAttribute(gemm1_kernel, cudaFuncAttributeMaxDynamicSharedMemorySize, SMEM_MAIN);
        attr_done = true;
    }

    void* xp; cudaGetSymbolAddress(&xp, g_Xh);
    void* wp; cudaGetSymbolAddress(&wp, g_Wh);

    perm_kernel<<<dim3(8, NROWS / 16 + DDIM / 16), 256>>>(x, W, (uint4*)xp, (uint4*)wp);

    dim3 grid(DDIM / BN, NROWS / BM);   // (16, 64)
    gemm1_kernel<<<grid, 256, SMEM_MAIN>>>();

    s12_kernel<<<NROWS / 8, 256>>>(a);
    prep_kernel<<<1, 1024>>>();
    rank2_kernel<<<NROWS / 256, 256>>>();
    sscan_kernel<<<1, 256>>>();
    cut_kernel<<<NROWS / 256, 256>>>();
    chunksum_kernel<<<dim3(DDIM / 512, NCHUNK), 256>>>();
    chunkscan_kernel<<<DDIM / 256, 256>>>();
    sweep_kernel<<<dim3(DDIM / 512, NCHUNK), 256>>>(out);
}